// round 17
// baseline (speedup 1.0000x reference)
#include <cuda_runtime.h>
#include <cuda_bf16.h>
#include <math.h>
#include <cstdint>

#define NMAX 50000

// ---------------------------------------------------------------------------
// Device scratch (allocation-free rule)
// ---------------------------------------------------------------------------
__device__ float g_agg[NMAX * 128];   // per-node aggregated messages (fp32)
__device__ float g_pacc[NMAX * 3];    // per-node position correction
__device__ float g_H1a[NMAX * 128];   // h @ W1a (sender half of edge stage-1)
__device__ float g_H1b[NMAX * 128];   // h @ W1b (receiver half)
__device__ float g_X1[NMAX * 128];    // h @ nW1a (node stage-1 h-part)
__device__ __nv_bfloat16 g_h_hi[NMAX * 128];
__device__ __nv_bfloat16 g_h_lo[NMAX * 128];
__device__ __nv_bfloat16 g_eW1t_hi[128 * 256];  // [n][k] transposed
__device__ __nv_bfloat16 g_eW1t_lo[128 * 256];
__device__ __nv_bfloat16 g_eW2t_hi[128 * 128];
__device__ __nv_bfloat16 g_eW2t_lo[128 * 128];
__device__ __nv_bfloat16 g_pW1t_hi[128 * 128];  // stage-3 is hh-only: no lo
__device__ __nv_bfloat16 g_nW1t_hi[128 * 256];
__device__ __nv_bfloat16 g_nW1t_lo[128 * 256];
__device__ __nv_bfloat16 g_nW2t_hi[128 * 128];
__device__ __nv_bfloat16 g_nW2t_lo[128 * 128];

__device__ __forceinline__ float silu_f(float x) {
    return x * __fdividef(1.0f, 1.0f + __expf(-x));
}

__device__ __forceinline__ uint32_t smem_u32(const void* p) {
    uint32_t a;
    asm("{ .reg .u64 t; cvta.to.shared.u64 t, %1; cvt.u32.u64 %0, t; }"
        : "=r"(a) : "l"(p));
    return a;
}

// ---- base-ISA async copy + vector reduction ----
__device__ __forceinline__ void cpa16(uint32_t smem, const void* g) {
    asm volatile("cp.async.cg.shared.global [%0], [%1], 16;"
                 :: "r"(smem), "l"(g) : "memory");
}
#define CPA_COMMIT() asm volatile("cp.async.commit_group;" ::: "memory")
#define CPA_WAIT(n)  asm volatile("cp.async.wait_group %0;" :: "n"(n) : "memory")

__device__ __forceinline__ unsigned long long pk2(float x, float y) {
    unsigned long long r;
    asm("mov.b64 %0, {%1, %2};" : "=l"(r) : "f"(x), "f"(y));
    return r;
}
// red.global.add.v4.f32 from two packed f32x2
__device__ __forceinline__ void red4f(float* addr,
                                      unsigned long long p,
                                      unsigned long long q) {
    float a, b, c, d;
    asm("mov.b64 {%0, %1}, %2;" : "=f"(a), "=f"(b) : "l"(p));
    asm("mov.b64 {%0, %1}, %2;" : "=f"(c), "=f"(d) : "l"(q));
    asm volatile("red.global.add.v4.f32 [%0], {%1, %2, %3, %4};"
                 :: "l"(addr), "f"(a), "f"(b), "f"(c), "f"(d) : "memory");
}

// ---- warp MMA primitives ----
__device__ __forceinline__ void ldsm4(uint32_t r[4], uint32_t addr) {
    asm volatile("ldmatrix.sync.aligned.m8n8.x4.shared.b16 {%0,%1,%2,%3}, [%4];"
                 : "=r"(r[0]), "=r"(r[1]), "=r"(r[2]), "=r"(r[3]) : "r"(addr));
}
__device__ __forceinline__ void mma_bf16(float d[4], const uint32_t a[4],
                                         uint32_t b0, uint32_t b1) {
    asm volatile(
        "mma.sync.aligned.m16n8k16.row.col.f32.bf16.bf16.f32 "
        "{%0,%1,%2,%3}, {%4,%5,%6,%7}, {%8,%9}, {%0,%1,%2,%3};"
        : "+f"(d[0]), "+f"(d[1]), "+f"(d[2]), "+f"(d[3])
        : "r"(a[0]), "r"(a[1]), "r"(a[2]), "r"(a[3]), "r"(b0), "r"(b1));
}

__device__ __forceinline__ void split_pack(float a, float b,
                                           uint32_t& hip, uint32_t& lop) {
    __nv_bfloat16 ah = __float2bfloat16(a);
    __nv_bfloat16 bh = __float2bfloat16(b);
    __nv_bfloat16 al = __float2bfloat16(a - __bfloat162float(ah));
    __nv_bfloat16 bl = __float2bfloat16(b - __bfloat162float(bh));
    __nv_bfloat162 hp, lp;
    hp.x = ah; hp.y = bh; lp.x = al; lp.y = bl;
    hip = *(uint32_t*)&hp;
    lop = *(uint32_t*)&lp;
}
__device__ __forceinline__ uint32_t pack_hi(float a, float b) {
    __nv_bfloat162 hp;
    hp.x = __float2bfloat16(a); hp.y = __float2bfloat16(b);
    return *(uint32_t*)&hp;
}

// One 64-deep K window, A from SMEM via ldmatrix: 3-pass hi/lo emulation.
__device__ __forceinline__ void mma_win64(uint32_t aH, uint32_t aL,
                                          uint32_t bH, uint32_t bL,
                                          float (*d)[4]) {
#pragma unroll
    for (int kk = 0; kk < 4; kk++) {
        uint32_t ah[4], al[4];
        ldsm4(ah, aH + kk * 32);
        ldsm4(al, aL + kk * 32);
#pragma unroll
        for (int np = 0; np < 8; np++) {
            uint32_t bh[4], bl[4];
            ldsm4(bh, bH + np * (16 * 144) + kk * 32);
            ldsm4(bl, bL + np * (16 * 144) + kk * 32);
            mma_bf16(d[2 * np],     ah, bh[0], bh[1]);
            mma_bf16(d[2 * np],     ah, bl[0], bl[1]);
            mma_bf16(d[2 * np],     al, bh[0], bh[1]);
            mma_bf16(d[2 * np + 1], ah, bh[2], bh[3]);
            mma_bf16(d[2 * np + 1], ah, bl[2], bl[3]);
            mma_bf16(d[2 * np + 1], al, bh[2], bh[3]);
        }
    }
}

// One K=16 chunk with register A fragments: 3-pass (hh+hl+lh)
__device__ __forceinline__ void mma_chunk3(const uint32_t ah[4], const uint32_t al[4],
                                           uint32_t bh0, uint32_t bl0,
                                           float (*e)[4]) {
#pragma unroll
    for (int np = 0; np < 8; np++) {
        uint32_t bh[4], bl[4];
        ldsm4(bh, bh0 + np * (16 * 144));
        ldsm4(bl, bl0 + np * (16 * 144));
        mma_bf16(e[2 * np],     ah, bh[0], bh[1]);
        mma_bf16(e[2 * np],     ah, bl[0], bl[1]);
        mma_bf16(e[2 * np],     al, bh[0], bh[1]);
        mma_bf16(e[2 * np + 1], ah, bh[2], bh[3]);
        mma_bf16(e[2 * np + 1], ah, bl[2], bl[3]);
        mma_bf16(e[2 * np + 1], al, bh[2], bh[3]);
    }
}
// One K=16 chunk, hh-only (stage 3)
__device__ __forceinline__ void mma_chunk1(const uint32_t ah[4], uint32_t bh0,
                                           float (*e)[4]) {
#pragma unroll
    for (int np = 0; np < 8; np++) {
        uint32_t bh[4];
        ldsm4(bh, bh0 + np * (16 * 144));
        mma_bf16(e[2 * np],     ah, bh[0], bh[1]);
        mma_bf16(e[2 * np + 1], ah, bh[2], bh[3]);
    }
}

// ---------------------------------------------------------------------------
// Prep kernel (zeroing fused)
// ---------------------------------------------------------------------------
__global__ void prep_kernel(const float* __restrict__ h,
                            const float* __restrict__ eW1,
                            const float* __restrict__ eW2,
                            const float* __restrict__ pW1,
                            const float* __restrict__ nW1,
                            const float* __restrict__ nW2, int N) {
    int i = blockIdx.x * blockDim.x + threadIdx.x;
    int stride = gridDim.x * blockDim.x;
    for (int k = i; k < N * 128; k += stride) {
        float v = h[k];
        __nv_bfloat16 hi = __float2bfloat16(v);
        g_h_hi[k] = hi;
        g_h_lo[k] = __float2bfloat16(v - __bfloat162float(hi));
        g_agg[k] = 0.f;
    }
    for (int k = i; k < N * 3; k += stride) g_pacc[k] = 0.f;
    for (int k = i; k < 128 * 256; k += stride) {
        int n = k >> 8, kk = k & 255;
        float v = eW1[kk * 128 + n];
        __nv_bfloat16 hi = __float2bfloat16(v);
        g_eW1t_hi[k] = hi;
        g_eW1t_lo[k] = __float2bfloat16(v - __bfloat162float(hi));
        float w = nW1[kk * 128 + n];
        __nv_bfloat16 wh = __float2bfloat16(w);
        g_nW1t_hi[k] = wh;
        g_nW1t_lo[k] = __float2bfloat16(w - __bfloat162float(wh));
    }
    for (int k = i; k < 128 * 128; k += stride) {
        int n = k >> 7, kk = k & 127;
        float v = eW2[kk * 128 + n];
        __nv_bfloat16 hi = __float2bfloat16(v);
        g_eW2t_hi[k] = hi;
        g_eW2t_lo[k] = __float2bfloat16(v - __bfloat162float(hi));
        g_pW1t_hi[k] = __float2bfloat16(pW1[kk * 128 + n]);
        float u = nW2[kk * 128 + n];
        __nv_bfloat16 uh = __float2bfloat16(u);
        g_nW2t_hi[k] = uh;
        g_nW2t_lo[k] = __float2bfloat16(u - __bfloat162float(uh));
    }
}

// ---------------------------------------------------------------------------
// h1_kernel: H1a = h@W1a, H1b = h@W1b, X1 = h@nW1a.
// A tiles resident; B streams 6 windows (3 mats x 2) double-buffered.
// ---------------------------------------------------------------------------
#define H1_A0H 0
#define H1_A0L 18432
#define H1_A1H 36864
#define H1_A1L 55296
#define H1_B0H 73728
#define H1_B0L 92160
#define H1_B1H 110592
#define H1_B1L 129024
#define H1_TOTAL 147456

__global__ __launch_bounds__(256, 1)
void h1_kernel(int N)
{
    extern __shared__ char sm[];
    const uint32_t smb = smem_u32(sm);
    const int tid = threadIdx.x;
    const int lane = tid & 31, w = tid >> 5;
    const int nb = blockIdx.x * 128;

    const int arow = lane & 15;
    const int akb = (lane >> 4) * 16;
    const int bn = (lane & 7) + ((lane >> 4) << 3);
    const int bkb = ((lane >> 3) & 1) * 16;

    const uint32_t aA_h[2] = {smb + H1_A0H + (w * 16 + arow) * 144 + akb,
                              smb + H1_A1H + (w * 16 + arow) * 144 + akb};
    const uint32_t aA_l[2] = {smb + H1_A0L + (w * 16 + arow) * 144 + akb,
                              smb + H1_A1L + (w * 16 + arow) * 144 + akb};
    const uint32_t aB_h[2] = {smb + H1_B0H + bn * 144 + bkb,
                              smb + H1_B1H + bn * 144 + bkb};
    const uint32_t aB_l[2] = {smb + H1_B0L + bn * 144 + bkb,
                              smb + H1_B1L + bn * 144 + bkb};

    const int r0 = w * 16 + (lane >> 2);
    const int r1 = r0 + 8;
    const int row2 = tid >> 1, half = tid & 1;

    const uint32_t dstAH[2] = {smb + H1_A0H + row2 * 144 + half * 64,
                               smb + H1_A1H + row2 * 144 + half * 64};
    const uint32_t dstAL[2] = {smb + H1_A0L + row2 * 144 + half * 64,
                               smb + H1_A1L + row2 * 144 + half * 64};
    const uint32_t dstBH[2] = {smb + H1_B0H + row2 * 144 + half * 64,
                               smb + H1_B1H + row2 * 144 + half * 64};
    const uint32_t dstBL[2] = {smb + H1_B0L + row2 * 144 + half * 64,
                               smb + H1_B1L + row2 * 144 + half * 64};

    int nodeA = nb + row2; if (nodeA >= N) nodeA = N - 1;

    const __nv_bfloat16* bh_base[3] = {g_eW1t_hi + row2 * 256,
                                       g_eW1t_hi + row2 * 256 + 128,
                                       g_nW1t_hi + row2 * 256};
    const __nv_bfloat16* bl_base[3] = {g_eW1t_lo + row2 * 256,
                                       g_eW1t_lo + row2 * 256 + 128,
                                       g_nW1t_lo + row2 * 256};
    float* outp[3] = {g_H1a, g_H1b, g_X1};

    auto issueB = [&](int m, int cw, int buf) {
        const __nv_bfloat16* swh = bh_base[m] + cw * 64 + half * 32;
        const __nv_bfloat16* swl = bl_base[m] + cw * 64 + half * 32;
#pragma unroll
        for (int t = 0; t < 4; t++) {
            cpa16(dstBH[buf] + t * 16, swh + t * 8);
            cpa16(dstBL[buf] + t * 16, swl + t * 8);
        }
        CPA_COMMIT();
    };

    // G0: A both windows + B win0 -> buf0
    {
#pragma unroll
        for (int cw = 0; cw < 2; cw++) {
            const __nv_bfloat16* shh = g_h_hi + nodeA * 128 + cw * 64 + half * 32;
            const __nv_bfloat16* shl = g_h_lo + nodeA * 128 + cw * 64 + half * 32;
#pragma unroll
            for (int t = 0; t < 4; t++) {
                cpa16(dstAH[cw] + t * 16, shh + t * 8);
                cpa16(dstAL[cw] + t * 16, shl + t * 8);
            }
        }
        const __nv_bfloat16* swh = bh_base[0] + half * 32;
        const __nv_bfloat16* swl = bl_base[0] + half * 32;
#pragma unroll
        for (int t = 0; t < 4; t++) {
            cpa16(dstBH[0] + t * 16, swh + t * 8);
            cpa16(dstBL[0] + t * 16, swl + t * 8);
        }
        CPA_COMMIT();
    }
    issueB(0, 1, 1);   // G1

    float d[16][4];
#pragma unroll
    for (int nt = 0; nt < 16; nt++)
#pragma unroll
        for (int q = 0; q < 4; q++) d[nt][q] = 0.f;

#pragma unroll
    for (int i = 0; i < 6; i++) {
        const int m = i >> 1, cw = i & 1, buf = i & 1;
        if (i < 5) { CPA_WAIT(1); } else { CPA_WAIT(0); }
        __syncthreads();
        mma_win64(aA_h[cw], aA_l[cw], aB_h[buf], aB_l[buf], d);
        if (cw == 1) {
            // write out[m], reset d
            int n0 = nb + r0, n1 = nb + r1;
            bool v0 = n0 < N, v1 = n1 < N;
            float* op = outp[m];
#pragma unroll
            for (int nt = 0; nt < 16; nt++) {
                int j = nt * 8 + (lane & 3) * 2;
                if (v0) *(float2*)&op[n0 * 128 + j] = make_float2(d[nt][0], d[nt][1]);
                if (v1) *(float2*)&op[n1 * 128 + j] = make_float2(d[nt][2], d[nt][3]);
                d[nt][0] = d[nt][1] = d[nt][2] = d[nt][3] = 0.f;
            }
        }
        __syncthreads();
        if (i + 2 <= 5) issueB((i + 2) >> 1, (i + 2) & 1, i & 1);
    }
}

// ---------------------------------------------------------------------------
// Edge kernel (persistent): 128 edges/tile, 256 threads.
// Stage 1 = gather H1a[s]+H1b[r] straight into D fragments (no MMA).
// eW2t (hi/lo) and pW1t (hh) SMEM-resident; agg scatter via red.v4 + shuffle.
// ---------------------------------------------------------------------------
#define R2H 0
#define R2L 36864
#define R3H 73728
#define EOFF_SE  110592
#define EOFF_RE  111104
#define EOFF_RAD 111616
#define EOFF_CD  112128
#define EOFF_EB1 113664
#define EOFF_EB2 114176
#define EOFF_PB1 114688
#define EOFF_PW2 115200
#define EOFF_W1R 115712
#define EOFF_RPC 116224
#define ESM_TOTAL 116736

__global__ __launch_bounds__(256, 1)
void edge_kernel(const float* __restrict__ pos,
                 const int* __restrict__ snd, const int* __restrict__ rcv,
                 const float* __restrict__ eW1, const float* __restrict__ eb1,
                 const float* __restrict__ eb2,
                 const float* __restrict__ pb1, const float* __restrict__ pW2,
                 int E, int nTiles)
{
    extern __shared__ char sm[];
    const uint32_t smb = smem_u32(sm);
    const int tid = threadIdx.x;
    const int lane = tid & 31, w = tid >> 5;

    int* se = (int*)(sm + EOFF_SE);
    int* re = (int*)(sm + EOFF_RE);
    float* rad = (float*)(sm + EOFF_RAD);
    float* cd = (float*)(sm + EOFF_CD);
    float* s_eb1 = (float*)(sm + EOFF_EB1);
    float* s_eb2 = (float*)(sm + EOFF_EB2);
    float* s_pb1 = (float*)(sm + EOFF_PB1);
    float* s_pw2 = (float*)(sm + EOFF_PW2);
    float* s_w1r = (float*)(sm + EOFF_W1R);
    float* redpc = (float*)(sm + EOFF_RPC);

    if (tid < 128) {
        s_eb1[tid] = eb1[tid];
        s_eb2[tid] = eb2[tid];
        s_pb1[tid] = pb1[tid];
        s_pw2[tid] = pW2[tid];
        s_w1r[tid] = eW1[256 * 128 + tid];
    }

    const int lane3 = lane & 3;
    const int bn = (lane & 7) + ((lane >> 4) << 3);
    const int bkb = ((lane >> 3) & 1) * 16;

    const uint32_t s2H[2] = {smb + R2H + bn * 144 + bkb,
                             smb + R2H + 18432 + bn * 144 + bkb};
    const uint32_t s2L[2] = {smb + R2L + bn * 144 + bkb,
                             smb + R2L + 18432 + bn * 144 + bkb};
    const uint32_t s3B[2] = {smb + R3H + bn * 144 + bkb,
                             smb + R3H + 18432 + bn * 144 + bkb};

    const int r0 = w * 16 + (lane >> 2);
    const int r1 = r0 + 8;
    const int row2 = tid >> 1, half = tid & 1;

    // resident weight load (once per CTA)
    {
#pragma unroll
        for (int cw = 0; cw < 2; cw++) {
            const __nv_bfloat16* s2h = g_eW2t_hi + row2 * 128 + cw * 64 + half * 32;
            const __nv_bfloat16* s2l = g_eW2t_lo + row2 * 128 + cw * 64 + half * 32;
            const __nv_bfloat16* s3h = g_pW1t_hi + row2 * 128 + cw * 64 + half * 32;
            uint32_t d2h = smb + R2H + cw * 18432 + row2 * 144 + half * 64;
            uint32_t d2l = smb + R2L + cw * 18432 + row2 * 144 + half * 64;
            uint32_t d3h = smb + R3H + cw * 18432 + row2 * 144 + half * 64;
#pragma unroll
            for (int t = 0; t < 4; t++) {
                cpa16(d2h + t * 16, s2h + t * 8);
                cpa16(d2l + t * 16, s2l + t * 8);
                cpa16(d3h + t * 16, s3h + t * 8);
            }
        }
        CPA_COMMIT();
        CPA_WAIT(0);
    }
    __syncthreads();

    const int qbase = lane & ~3;
    const int srcb = qbase | ((lane3 & 1) << 1);
    const bool lohalf = lane3 < 2;

    for (int tile = blockIdx.x; tile < nTiles; tile += gridDim.x) {
        const int ebase = tile * 128;
        if (tid < 128) {
            int ge = ebase + tid; if (ge >= E) ge = E - 1;
            int s = snd[ge], r = rcv[ge];
            se[tid] = s; re[tid] = r;
            float dx = pos[s * 3 + 0] - pos[r * 3 + 0];
            float dy = pos[s * 3 + 1] - pos[r * 3 + 1];
            float dz = pos[s * 3 + 2] - pos[r * 3 + 2];
            cd[tid * 3 + 0] = dx; cd[tid * 3 + 1] = dy; cd[tid * 3 + 2] = dz;
            rad[tid] = dx * dx + dy * dy + dz * dz;
        }
        __syncthreads();

        // ===== stage 1: gather H1a[s] + H1b[r] into D fragments =====
        const int s0 = se[r0], s1 = se[r1];
        const int q0 = re[r0], q1 = re[r1];
        float d[16][4];
#pragma unroll
        for (int nt = 0; nt < 16; nt++) {
            int j = nt * 8 + lane3 * 2;
            float2 a0 = *(const float2*)&g_H1a[s0 * 128 + j];
            float2 b0 = *(const float2*)&g_H1b[q0 * 128 + j];
            float2 a1 = *(const float2*)&g_H1a[s1 * 128 + j];
            float2 b1 = *(const float2*)&g_H1b[q1 * 128 + j];
            d[nt][0] = a0.x + b0.x; d[nt][1] = a0.y + b0.y;
            d[nt][2] = a1.x + b1.x; d[nt][3] = a1.y + b1.y;
        }

        // ===== fused ep1 + stage2 =====
        float e[16][4];
#pragma unroll
        for (int nt = 0; nt < 16; nt++)
#pragma unroll
            for (int q = 0; q < 4; q++) e[nt][q] = 0.f;
        const float rd0 = rad[r0], rd1 = rad[r1];
#pragma unroll
        for (int c = 0; c < 8; c++) {
            int nt0 = 2 * c, nt1 = 2 * c + 1;
            int j0 = nt0 * 8 + lane3 * 2;
            int j1 = j0 + 8;
            uint32_t ah[4], al[4];
            float v00 = silu_f(d[nt0][0] + rd0 * s_w1r[j0] + s_eb1[j0]);
            float v01 = silu_f(d[nt0][1] + rd0 * s_w1r[j0 + 1] + s_eb1[j0 + 1]);
            float v10 = silu_f(d[nt0][2] + rd1 * s_w1r[j0] + s_eb1[j0]);
            float v11 = silu_f(d[nt0][3] + rd1 * s_w1r[j0 + 1] + s_eb1[j0 + 1]);
            split_pack(v00, v01, ah[0], al[0]);
            split_pack(v10, v11, ah[1], al[1]);
            float w00 = silu_f(d[nt1][0] + rd0 * s_w1r[j1] + s_eb1[j1]);
            float w01 = silu_f(d[nt1][1] + rd0 * s_w1r[j1 + 1] + s_eb1[j1 + 1]);
            float w10 = silu_f(d[nt1][2] + rd1 * s_w1r[j1] + s_eb1[j1]);
            float w11 = silu_f(d[nt1][3] + rd1 * s_w1r[j1 + 1] + s_eb1[j1 + 1]);
            split_pack(w00, w01, ah[2], al[2]);
            split_pack(w10, w11, ah[3], al[3]);
            mma_chunk3(ah, al, s2H[c >> 2] + (c & 3) * 32,
                       s2L[c >> 2] + (c & 3) * 32, e);
        }

        // ===== fused ep2 + red.v4 agg scatter + stage3 (hh-only) =====
#pragma unroll
        for (int nt = 0; nt < 16; nt++)
#pragma unroll
            for (int q = 0; q < 4; q++) d[nt][q] = 0.f;
        {
            bool val0 = (ebase + r0) < E, val1 = (ebase + r1) < E;
            const int rn = lohalf ? q0 : q1;
            const bool val = lohalf ? val0 : val1;
#pragma unroll
            for (int c = 0; c < 8; c++) {
                int nt0 = 2 * c, nt1 = 2 * c + 1;
                int j0 = nt0 * 8 + lane3 * 2;
                int j1 = j0 + 8;
                uint32_t ah[4];
                float v00 = silu_f(e[nt0][0] + s_eb2[j0]);
                float v01 = silu_f(e[nt0][1] + s_eb2[j0 + 1]);
                float v10 = silu_f(e[nt0][2] + s_eb2[j0]);
                float v11 = silu_f(e[nt0][3] + s_eb2[j0 + 1]);
                float w00 = silu_f(e[nt1][0] + s_eb2[j1]);
                float w01 = silu_f(e[nt1][1] + s_eb2[j1 + 1]);
                float w10 = silu_f(e[nt1][2] + s_eb2[j1]);
                float w11 = silu_f(e[nt1][3] + s_eb2[j1 + 1]);
                ah[0] = pack_hi(v00, v01);
                ah[1] = pack_hi(v10, v11);
                ah[2] = pack_hi(w00, w01);
                ah[3] = pack_hi(w10, w11);
                // quad transpose -> one red.v4 per lane per 8-col block
                {
                    unsigned long long A0 = pk2(v00, v01), A1 = pk2(v10, v11);
                    unsigned long long W0 = pk2(w00, w01), W1 = pk2(w10, w11);
                    unsigned long long pa0 = __shfl_sync(0xffffffffu, A0, srcb);
                    unsigned long long pa1 = __shfl_sync(0xffffffffu, A0, srcb + 1);
                    unsigned long long pb0 = __shfl_sync(0xffffffffu, A1, srcb);
                    unsigned long long pb1 = __shfl_sync(0xffffffffu, A1, srcb + 1);
                    unsigned long long x0 = lohalf ? pa0 : pb0;
                    unsigned long long x1 = lohalf ? pa1 : pb1;
                    int cb = nt0 * 8 + (lane3 & 1) * 4;
                    if (val) red4f(&g_agg[rn * 128 + cb], x0, x1);
                    pa0 = __shfl_sync(0xffffffffu, W0, srcb);
                    pa1 = __shfl_sync(0xffffffffu, W0, srcb + 1);
                    pb0 = __shfl_sync(0xffffffffu, W1, srcb);
                    pb1 = __shfl_sync(0xffffffffu, W1, srcb + 1);
                    x0 = lohalf ? pa0 : pb0;
                    x1 = lohalf ? pa1 : pb1;
                    if (val) red4f(&g_agg[rn * 128 + cb + 8], x0, x1);
                }
                mma_chunk1(ah, s3B[c >> 2] + (c & 3) * 32, d);
            }
        }

        // ===== ep3: pc reduction + position scatter =====
        {
            float p0 = 0.f, p1 = 0.f;
#pragma unroll
            for (int nt = 0; nt < 16; nt++) {
                int j = nt * 8 + lane3 * 2;
                p0 += silu_f(d[nt][0] + s_pb1[j]) * s_pw2[j]
                    + silu_f(d[nt][1] + s_pb1[j + 1]) * s_pw2[j + 1];
                p1 += silu_f(d[nt][2] + s_pb1[j]) * s_pw2[j]
                    + silu_f(d[nt][3] + s_pb1[j + 1]) * s_pw2[j + 1];
            }
            p0 += __shfl_xor_sync(0xffffffffu, p0, 1);
            p0 += __shfl_xor_sync(0xffffffffu, p0, 2);
            p1 += __shfl_xor_sync(0xffffffffu, p1, 1);
            p1 += __shfl_xor_sync(0xffffffffu, p1, 2);
            if ((lane & 3) == 0) { redpc[r0] = p0; redpc[r1] = p1; }
            __syncthreads();
            if (tid < 128 && (ebase + tid) < E) {
                int s = se[tid];
                float pc = redpc[tid];
#pragma unroll
                for (int dd = 0; dd < 3; dd++) {
                    float v = cd[tid * 3 + dd] * pc;
                    v = fminf(fmaxf(v, -100.f), 100.f);
                    atomicAdd(&g_pacc[s * 3 + dd], v);
                }
            }
        }
        __syncthreads();   // se/re/rad/cd/redpc reuse safety
    }
}

// ---------------------------------------------------------------------------
// Node kernel: d init from X1; stage-1 = agg@nW1b only (agg split in-register);
// all weights SMEM-resident upfront.
// ---------------------------------------------------------------------------
#define NA0H 0
#define NA0L 18432
#define NA1H 36864
#define NA1L 55296
#define NB0H 73728
#define NB0L 92160
#define NB1H 110592
#define NB1L 129024
#define NC0H 147456
#define NC0L 165888
#define NC1H 184320
#define NC1L 202752
#define NOD_NB1 221184
#define NOD_NB2 221696
#define NOD_TOTAL 222208

__global__ __launch_bounds__(256, 1)
void node_kernel(const float* __restrict__ h, const float* __restrict__ pos,
                 const float* __restrict__ nb1, const float* __restrict__ nb2,
                 float* __restrict__ out, int N)
{
    extern __shared__ char sm[];
    const uint32_t smb = smem_u32(sm);
    const int tid = threadIdx.x;
    const int lane = tid & 31, w = tid >> 5;
    const int nb = blockIdx.x * 128;

    float* s_nb1 = (float*)(sm + NOD_NB1);
    float* s_nb2 = (float*)(sm + NOD_NB2);
    if (tid < 128) {
        s_nb1[tid] = nb1[tid];
        s_nb2[tid] = nb2[tid];
    }

    const int arow = lane & 15;
    const int akb = (lane >> 4) * 16;
    const int bn = (lane & 7) + ((lane >> 4) << 3);
    const int bkb = ((lane >> 3) & 1) * 16;

    const uint32_t aA_h[2] = {smb + NA0H + (w * 16 + arow) * 144 + akb,
                              smb + NA1H + (w * 16 + arow) * 144 + akb};
    const uint32_t aA_l[2] = {smb + NA0L + (w * 16 + arow) * 144 + akb,
                              smb + NA1L + (w * 16 + arow) * 144 + akb};
    const uint32_t aB_h[2] = {smb + NB0H + bn * 144 + bkb,
                              smb + NB1H + bn * 144 + bkb};
    const uint32_t aB_l[2] = {smb + NB0L + bn * 144 + bkb,
                              smb + NB1L + bn * 144 + bkb};
    const uint32_t s2H[2] = {smb + NC0H + bn * 144 + bkb,
                             smb + NC1H + bn * 144 + bkb};
    const uint32_t s2L[2] = {smb + NC0L + bn * 144 + bkb,
                             smb + NC1L + bn * 144 + bkb};

    const int r0 = w * 16 + (lane >> 2);
    const int r1 = r0 + 8;
    const int row2 = tid >> 1, half = tid & 1;

    int nodeA = nb + row2; if (nodeA >= N) nodeA = N - 1;

    // cp.async all weights (nW1b windows + nW2t windows)
    {
#pragma unroll
        for (int cw = 0; cw < 2; cw++) {
            const __nv_bfloat16* b1h = g_nW1t_hi + row2 * 256 + 128 + cw * 64 + half * 32;
            const __nv_bfloat16* b1l = g_nW1t_lo + row2 * 256 + 128 + cw * 64 + half * 32;
            const __nv_bfloat16* c2h = g_nW2t_hi + row2 * 128 + cw * 64 + half * 32;
            const __nv_bfloat16* c2l = g_nW2t_lo + row2 * 128 + cw * 64 + half * 32;
            uint32_t dbh = smb + (cw ? NB1H : NB0H) + row2 * 144 + half * 64;
            uint32_t dbl = smb + (cw ? NB1L : NB0L) + row2 * 144 + half * 64;
            uint32_t dch = smb + (cw ? NC1H : NC0H) + row2 * 144 + half * 64;
            uint32_t dcl = smb + (cw ? NC1L : NC0L) + row2 * 144 + half * 64;
#pragma unroll
            for (int t = 0; t < 4; t++) {
                cpa16(dbh + t * 16, b1h + t * 8);
                cpa16(dbl + t * 16, b1l + t * 8);
                cpa16(dch + t * 16, c2h + t * 8);
                cpa16(dcl + t * 16, c2l + t * 8);
            }
        }
        CPA_COMMIT();
    }

    // load agg fp32, split in-register, STS into A tiles
    {
#pragma unroll
        for (int cw = 0; cw < 2; cw++) {
            const float4* src = (const float4*)(g_agg + nodeA * 128 + cw * 64 + half * 32);
            uint32_t hibuf[16], lobuf[16];
#pragma unroll
            for (int t = 0; t < 8; t++) {
                float4 v = src[t];
                split_pack(v.x, v.y, hibuf[2 * t], lobuf[2 * t]);
                split_pack(v.z, v.w, hibuf[2 * t + 1], lobuf[2 * t + 1]);
            }
            uint32_t dah = smb + (cw ? NA1H : NA0H) + row2 * 144 + half * 64;
            uint32_t dal = smb + (cw ? NA1L : NA0L) + row2 * 144 + half * 64;
#pragma unroll
            for (int t = 0; t < 4; t++) {
                *(uint4*)(sm + (dah - smb) + t * 16) =
                    make_uint4(hibuf[4 * t], hibuf[4 * t + 1], hibuf[4 * t + 2], hibuf[4 * t + 3]);
                *(uint4*)(sm + (dal - smb) + t * 16) =
                    make_uint4(lobuf[4 * t], lobuf[4 * t + 1], lobuf[4 * t + 2], lobuf[4 * t + 3]);
            }
        }
    }

    // init d from X1
    float d[16][4];
    {
        int n0 = nb + r0, n1 = nb + r1;
        bool v0 = n0 < N, v1 = n1 < N;
#pragma unroll
        for (int nt = 0; nt < 16; nt++) {
            int j = nt * 8 + (lane & 3) * 2;
            float2 x0 = v0 ? *(const float2*)&g_X1[n0 * 128 + j] : make_float2(0.f, 0.f);
            float2 x1 = v1 ? *(const float2*)&g_X1[n1 * 128 + j] : make_float2(0.f, 0.f);
            d[nt][0] = x0.x; d[nt][1] = x0.y;
            d[nt][2] = x1.x; d[nt][3] = x1.y;
        }
    }

    CPA_WAIT(0);
    __syncthreads();

    // stage 1: += agg @ nW1b (2 windows)
    mma_win64(aA_h[0], aA_l[0], aB_h[0], aB_l[0], d);
    mma_win64(aA_h[1], aA_l[1], aB_h[1], aB_l[1], d);

    // fused ep1 + stage2 (3-pass)
    float e[16][4];
#pragma unroll
    for (int nt = 0; nt < 16; nt++)
#pragma unroll
        for (int q = 0; q < 4; q++) e[nt][q] = 0.f;
#pragma unroll
    for (int c = 0; c < 8; c++) {
        int nt0 = 2 * c, nt1 = 2 * c + 1;
        int j0 = nt0 * 8 + (lane & 3) * 2;
        int j1 = j0 + 8;
        uint32_t ah[4], al[4];
        float v00 = silu_f(d[nt0][0] + s_nb1[j0]);
        float v01 = silu_f(d[nt0][1] + s_nb1[j0 + 1]);
        float v10 = silu_f(d[nt0][2] + s_nb1[j0]);
        float v11 = silu_f(d[nt0][3] + s_nb1[j0 + 1]);
        split_pack(v00, v01, ah[0], al[0]);
        split_pack(v10, v11, ah[1], al[1]);
        float w00 = silu_f(d[nt1][0] + s_nb1[j1]);
        float w01 = silu_f(d[nt1][1] + s_nb1[j1 + 1]);
        float w10 = silu_f(d[nt1][2] + s_nb1[j1]);
        float w11 = silu_f(d[nt1][3] + s_nb1[j1 + 1]);
        split_pack(w00, w01, ah[2], al[2]);
        split_pack(w10, w11, ah[3], al[3]);
        mma_chunk3(ah, al, s2H[c >> 2] + (c & 3) * 32,
                   s2L[c >> 2] + (c & 3) * 32, e);
    }

    // epilogue: h_new = h + x
    {
        int n0 = nb + r0, n1 = nb + r1;
        bool v0 = n0 < N, v1 = n1 < N;
#pragma unroll
        for (int nt = 0; nt < 16; nt++) {
            int j = nt * 8 + (lane & 3) * 2;
            if (v0) {
                out[n0 * 128 + j]     = e[nt][0] + s_nb2[j] + h[n0 * 128 + j];
                out[n0 * 128 + j + 1] = e[nt][1] + s_nb2[j + 1] + h[n0 * 128 + j + 1];
            }
            if (v1) {
                out[n1 * 128 + j]     = e[nt][2] + s_nb2[j] + h[n1 * 128 + j];
                out[n1 * 128 + j + 1] = e[nt][3] + s_nb2[j + 1] + h[n1 * 128 + j + 1];
            }
        }
    }

    // pos_new = pos + pacc
    if (tid < 128) {
        int node = nb + tid;
        if (node < N) {
#pragma unroll
            for (int dd = 0; dd < 3; dd++)
                out[N * 128 + node * 3 + dd] =
                    pos[node * 3 + dd] + g_pacc[node * 3 + dd];
        }
    }
}

extern "C" void kernel_launch(void* const* d_in, const int* in_sizes, int n_in,
                              void* d_out, int out_size)
{
    const float* h   = (const float*)d_in[0];
    const float* pos = (const float*)d_in[1];
    const int*   snd = (const int*)d_in[2];
    const int*   rcv = (const int*)d_in[3];
    const float* eW1 = (const float*)d_in[4];
    const float* eb1 = (const float*)d_in[5];
    const float* eW2 = (const float*)d_in[6];
    const float* eb2 = (const float*)d_in[7];
    const float* nW1 = (const float*)d_in[8];
    const float* nb1 = (const float*)d_in[9];
    const float* nW2 = (const float*)d_in[10];
    const float* nb2 = (const float*)d_in[11];
    const float* pW1 = (const float*)d_in[12];
    const float* pb1 = (const float*)d_in[13];
    const float* pW2 = (const float*)d_in[14];
    float* out = (float*)d_out;

    int N = in_sizes[0] / 128;
    int E = in_sizes[2];
    int nTiles = (E + 127) / 128;
    int nBlocks = (N + 127) / 128;

    cudaFuncSetAttribute(h1_kernel, cudaFuncAttributeMaxDynamicSharedMemorySize, H1_TOTAL);
    cudaFuncSetAttribute(edge_kernel, cudaFuncAttributeMaxDynamicSharedMemorySize, ESM_TOTAL);
    cudaFuncSetAttribute(node_kernel, cudaFuncAttributeMaxDynamicSharedMemorySize, NOD_TOTAL);

    prep_kernel<<<512, 256>>>(h, eW1, eW2, pW1, nW1, nW2, N);
    h1_kernel<<<nBlocks, 256, H1_TOTAL>>>(N);
    int grid = nTiles < 152 ? nTiles : 152;
    edge_kernel<<<grid, 256, ESM_TOTAL>>>(pos, snd, rcv, eW1, eb1, eb2,
                                          pb1, pW2, E, nTiles);
    node_kernel<<<nBlocks, 256, NOD_TOTAL>>>(h, pos, nb1, nb2, out, N);
}